// round 5
// baseline (speedup 1.0000x reference)
#include <cuda_runtime.h>

// Loss: per joint (3 floats): d = p - l; s2 = d2^2;
// term = (p2 > 0.5) ? (d0^2+d1^2+d2^2)/3 : s2 ; answer = sum(term)/B.
// Layout: [B, 54] fp32 -> B*18 joints; 4 joints = 3 float4 per group.
// Work distribution: each WARP owns a contiguous range of groups
// (base + at-most-1 extra), eliminating the 2.8% ceil-skew of the
// grid-stride loop. Lanes process consecutive groups -> same coalescing.

__device__ __forceinline__ float joint_term(float p0, float p1, float p2,
                                            float l0, float l1, float l2) {
    float d0 = p0 - l0, d1 = p1 - l1, d2 = p2 - l2;
    float s2 = d2 * d2;
    float full = (d0 * d0 + d1 * d1 + s2) * (1.0f / 3.0f);
    return (p2 > 0.5f) ? full : s2;
}

__device__ __forceinline__ float group4(const float4* __restrict__ P,
                                        const float4* __restrict__ L,
                                        int g) {
    int base = 3 * g;
    float4 pa = P[base + 0];
    float4 pb = P[base + 1];
    float4 pc = P[base + 2];
    float4 la = L[base + 0];
    float4 lb = L[base + 1];
    float4 lc = L[base + 2];
    float acc;
    acc  = joint_term(pa.x, pa.y, pa.z, la.x, la.y, la.z);
    acc += joint_term(pa.w, pb.x, pb.y, la.w, lb.x, lb.y);
    acc += joint_term(pb.z, pb.w, pc.x, lb.z, lb.w, lc.x);
    acc += joint_term(pc.y, pc.z, pc.w, lc.y, lc.z, lc.w);
    return acc;
}

__global__ void __launch_bounds__(256)
loss_kernel(const float4* __restrict__ P, const float4* __restrict__ L,
            float* __restrict__ out, int ngroups, float inv_b) {
    int lane  = threadIdx.x & 31;
    int wid   = threadIdx.x >> 5;
    int gwarp = (blockIdx.x * blockDim.x + threadIdx.x) >> 5;
    int W     = (gridDim.x * blockDim.x) >> 5;

    // contiguous per-warp range: base groups each, first `rem` warps get +1
    int base  = ngroups / W;
    int rem   = ngroups - base * W;
    int start = gwarp * base + (gwarp < rem ? gwarp : rem);
    int count = base + (gwarp < rem ? 1 : 0);

    float acc = 0.0f;
    int full  = count >> 5;          // full passes of 32 groups
    int g     = start + lane;
    for (int it = 0; it < full; ++it, g += 32)
        acc += group4(P, L, g);
    if (lane < (count & 31))         // predicated tail pass
        acc += group4(P, L, g);

    // warp reduce
    #pragma unroll
    for (int off = 16; off; off >>= 1)
        acc += __shfl_down_sync(0xFFFFFFFFu, acc, off);

    __shared__ float ws[8];
    if (lane == 0) ws[wid] = acc;
    __syncthreads();
    if (wid == 0) {
        acc = (lane < 8) ? ws[lane] : 0.0f;
        #pragma unroll
        for (int off = 4; off; off >>= 1)
            acc += __shfl_down_sync(0xFFFFFFFFu, acc, off);
        if (lane == 0) atomicAdd(out, acc * inv_b);
    }
}

extern "C" void kernel_launch(void* const* d_in, const int* in_sizes, int n_in,
                              void* d_out, int out_size) {
    const float4* P = (const float4*)d_in[0];
    const float4* L = (const float4*)d_in[1];
    float* out = (float*)d_out;

    long long total_floats = (long long)in_sizes[0];   // B * 54
    long long B = total_floats / 54;
    int ngroups = (int)(total_floats / 12);            // 4-joint groups

    cudaMemsetAsync(out, 0, sizeof(float));

    const int threads = 256;
    const int blocks  = 148 * 8;                       // one wave, 9472 warps
    loss_kernel<<<blocks, threads>>>(P, L, out, ngroups, 1.0f / (float)B);
}

// round 6
// speedup vs baseline: 1.0642x; 1.0642x over previous
#include <cuda_runtime.h>

// Loss: per joint (3 floats): d = p - l; s2 = d2^2;
// term = (p2 > 0.5) ? (d0^2+d1^2+d2^2)/3 : s2 ; answer = sum(term)/B.
// Layout: [B, 54] fp32 -> B*18 joints of 3 floats; 4 joints = 3 float4 per
// thread-iteration. Grid-stride (dense sweeping window -> best DRAM page /
// L2 locality, proven over per-warp blocking in R5), single wave
// (148 SMs x 8 CTAs x 256 thr), per-block atomicAdd, memset init node.

__device__ __forceinline__ float joint_term(float p0, float p1, float p2,
                                            float l0, float l1, float l2) {
    float d0 = p0 - l0, d1 = p1 - l1, d2 = p2 - l2;
    float s2 = d2 * d2;
    float full = (d0 * d0 + d1 * d1 + s2) * (1.0f / 3.0f);
    return (p2 > 0.5f) ? full : s2;
}

__global__ void __launch_bounds__(256)
loss_kernel(const float4* __restrict__ P, const float4* __restrict__ L,
            float* __restrict__ out, int ngroups, float inv_b) {
    float acc = 0.0f;
    int stride = gridDim.x * blockDim.x;
    #pragma unroll 1
    for (int g = blockIdx.x * blockDim.x + threadIdx.x; g < ngroups; g += stride) {
        int base = 3 * g;
        float4 pa = P[base + 0];
        float4 pb = P[base + 1];
        float4 pc = P[base + 2];
        float4 la = L[base + 0];
        float4 lb = L[base + 1];
        float4 lc = L[base + 2];
        acc += joint_term(pa.x, pa.y, pa.z, la.x, la.y, la.z);
        acc += joint_term(pa.w, pb.x, pb.y, la.w, lb.x, lb.y);
        acc += joint_term(pb.z, pb.w, pc.x, lb.z, lb.w, lc.x);
        acc += joint_term(pc.y, pc.z, pc.w, lc.y, lc.z, lc.w);
    }

    // warp reduce
    #pragma unroll
    for (int off = 16; off; off >>= 1)
        acc += __shfl_down_sync(0xFFFFFFFFu, acc, off);

    __shared__ float ws[8];
    int lane = threadIdx.x & 31;
    int wid  = threadIdx.x >> 5;
    if (lane == 0) ws[wid] = acc;
    __syncthreads();
    if (wid == 0) {
        acc = (lane < 8) ? ws[lane] : 0.0f;
        #pragma unroll
        for (int off = 4; off; off >>= 1)
            acc += __shfl_down_sync(0xFFFFFFFFu, acc, off);
        if (lane == 0) atomicAdd(out, acc * inv_b);
    }
}

extern "C" void kernel_launch(void* const* d_in, const int* in_sizes, int n_in,
                              void* d_out, int out_size) {
    const float4* P = (const float4*)d_in[0];
    const float4* L = (const float4*)d_in[1];
    float* out = (float*)d_out;

    long long total_floats = (long long)in_sizes[0];   // B * 54
    long long B = total_floats / 54;
    int ngroups = (int)(total_floats / 12);            // 4-joint groups

    cudaMemsetAsync(out, 0, sizeof(float));

    const int threads = 256;
    const int blocks  = 148 * 8;                       // exactly one wave
    loss_kernel<<<blocks, threads>>>(P, L, out, ngroups, 1.0f / (float)B);
}

// round 7
// speedup vs baseline: 1.0861x; 1.0205x over previous
#include <cuda_runtime.h>

// Loss: per joint (3 floats): d = p - l; s2 = d2^2;
// term = (p2 > 0.5) ? (d0^2+d1^2+d2^2)/3 : s2 ; answer = sum(term)/B.
// Layout: [B, 54] fp32 -> B*18 joints of 3 floats; 4 joints = 3 float4 per
// thread-iteration. Grid-stride loop with compiler-chosen unrolling (R6
// proved forcing unroll-1 costs ~3us of MLP), single wave (148x8x256),
// per-block atomicAdd into d_out, memset graph node for init.

__device__ __forceinline__ float joint_term(float p0, float p1, float p2,
                                            float l0, float l1, float l2) {
    float d0 = p0 - l0, d1 = p1 - l1, d2 = p2 - l2;
    float s2 = d2 * d2;
    float full = (d0 * d0 + d1 * d1 + s2) * (1.0f / 3.0f);
    return (p2 > 0.5f) ? full : s2;
}

__global__ void __launch_bounds__(256)
loss_kernel(const float4* __restrict__ P, const float4* __restrict__ L,
            float* __restrict__ out, int ngroups, float inv_b) {
    float acc = 0.0f;
    int stride = gridDim.x * blockDim.x;
    for (int g = blockIdx.x * blockDim.x + threadIdx.x; g < ngroups; g += stride) {
        int base = 3 * g;
        float4 pa = P[base + 0];
        float4 pb = P[base + 1];
        float4 pc = P[base + 2];
        float4 la = L[base + 0];
        float4 lb = L[base + 1];
        float4 lc = L[base + 2];
        acc += joint_term(pa.x, pa.y, pa.z, la.x, la.y, la.z);
        acc += joint_term(pa.w, pb.x, pb.y, la.w, lb.x, lb.y);
        acc += joint_term(pb.z, pb.w, pc.x, lb.z, lb.w, lc.x);
        acc += joint_term(pc.y, pc.z, pc.w, lc.y, lc.z, lc.w);
    }

    // warp reduce
    #pragma unroll
    for (int off = 16; off; off >>= 1)
        acc += __shfl_down_sync(0xFFFFFFFFu, acc, off);

    __shared__ float ws[8];
    int lane = threadIdx.x & 31;
    int wid  = threadIdx.x >> 5;
    if (lane == 0) ws[wid] = acc;
    __syncthreads();
    if (wid == 0) {
        acc = (lane < 8) ? ws[lane] : 0.0f;
        #pragma unroll
        for (int off = 4; off; off >>= 1)
            acc += __shfl_down_sync(0xFFFFFFFFu, acc, off);
        if (lane == 0) atomicAdd(out, acc * inv_b);
    }
}

extern "C" void kernel_launch(void* const* d_in, const int* in_sizes, int n_in,
                              void* d_out, int out_size) {
    const float4* P = (const float4*)d_in[0];
    const float4* L = (const float4*)d_in[1];
    float* out = (float*)d_out;

    long long total_floats = (long long)in_sizes[0];   // B * 54
    long long B = total_floats / 54;
    int ngroups = (int)(total_floats / 12);            // 4-joint groups

    cudaMemsetAsync(out, 0, sizeof(float));

    const int threads = 256;
    const int blocks  = 148 * 8;                       // exactly one wave
    loss_kernel<<<blocks, threads>>>(P, L, out, ngroups, 1.0f / (float)B);
}

// round 8
// speedup vs baseline: 1.1104x; 1.0223x over previous
#include <cuda_runtime.h>

// Loss: per joint (3 floats): d = p - l; s2 = d2^2;
// term = (p2 > 0.5) ? (d0^2+d1^2+d2^2)/3 : s2 ; answer = sum(term)/B.
// Layout: [B, 54] fp32 -> B*18 joints of 3 floats; 4 joints = 3 float4 per
// thread-iteration. Champion configuration (R1): grid-stride loop with
// compiler-chosen unrolling, grid 148*16, per-block atomicAdd, init kernel.
// Measured at the achieved-HBM ceiling (~6.6 TB/s, 83% of spec); all
// structural variants tested in R2-R7 were neutral or regressions.

__device__ __forceinline__ float joint_term(float p0, float p1, float p2,
                                            float l0, float l1, float l2) {
    float d0 = p0 - l0, d1 = p1 - l1, d2 = p2 - l2;
    float s2 = d2 * d2;
    float full = (d0 * d0 + d1 * d1 + s2) * (1.0f / 3.0f);
    return (p2 > 0.5f) ? full : s2;
}

__global__ void init_out_kernel(float* out) {
    if (threadIdx.x == 0) out[0] = 0.0f;
}

__global__ void __launch_bounds__(256)
loss_kernel(const float4* __restrict__ P, const float4* __restrict__ L,
            float* __restrict__ out, int ngroups, float inv_b) {
    float acc = 0.0f;
    int stride = gridDim.x * blockDim.x;
    for (int g = blockIdx.x * blockDim.x + threadIdx.x; g < ngroups; g += stride) {
        int base = 3 * g;
        float4 pa = P[base + 0];
        float4 pb = P[base + 1];
        float4 pc = P[base + 2];
        float4 la = L[base + 0];
        float4 lb = L[base + 1];
        float4 lc = L[base + 2];
        // 4 joints packed across the 3 float4s
        acc += joint_term(pa.x, pa.y, pa.z, la.x, la.y, la.z);
        acc += joint_term(pa.w, pb.x, pb.y, la.w, lb.x, lb.y);
        acc += joint_term(pb.z, pb.w, pc.x, lb.z, lb.w, lc.x);
        acc += joint_term(pc.y, pc.z, pc.w, lc.y, lc.z, lc.w);
    }

    // warp reduce
    #pragma unroll
    for (int off = 16; off; off >>= 1)
        acc += __shfl_down_sync(0xFFFFFFFFu, acc, off);

    __shared__ float ws[8];
    int lane = threadIdx.x & 31;
    int wid  = threadIdx.x >> 5;
    if (lane == 0) ws[wid] = acc;
    __syncthreads();
    if (wid == 0) {
        acc = (lane < 8) ? ws[lane] : 0.0f;
        #pragma unroll
        for (int off = 4; off; off >>= 1)
            acc += __shfl_down_sync(0xFFFFFFFFu, acc, off);
        if (lane == 0) atomicAdd(out, acc * inv_b);
    }
}

extern "C" void kernel_launch(void* const* d_in, const int* in_sizes, int n_in,
                              void* d_out, int out_size) {
    const float4* P = (const float4*)d_in[0];
    const float4* L = (const float4*)d_in[1];
    float* out = (float*)d_out;

    long long total_floats = (long long)in_sizes[0];     // B * 54
    long long B = total_floats / 54;
    int ngroups = (int)(total_floats / 12);              // 4-joint groups

    init_out_kernel<<<1, 32>>>(out);

    const int threads = 256;
    const int blocks = 148 * 16;                         // champion grid
    loss_kernel<<<blocks, threads>>>(P, L, out, ngroups, 1.0f / (float)B);
}